// round 15
// baseline (speedup 1.0000x reference)
#include <cuda_runtime.h>
#include <cuda_bf16.h>
#include <math.h>

#define N_NODES 50000
#define N_EDGES 800000
#define IN_DIM 512
#define HID_DIM 64
#define OUT_DIM 40
#define SCAN_NB ((N_NODES + 255) / 256)   // 196

// ---------------- scratch (no allocations allowed) ----------------
__device__ float g_h1[N_NODES * HID_DIM];     // x @ W1
__device__ float g_h2[N_NODES * OUT_DIM];     // relu(agg1) @ W2
__device__ float g_w1t[HID_DIM * IN_DIM];     // W1 tf32, transposed + pair-interleaved
__device__ int   g_csr[N_EDGES];              // src ids grouped by dst
__device__ int   g_cnt[N_NODES];              // per-dst degree (zeroed inside scan)
__device__ int   g_rowstart[N_NODES + 1];
__device__ int   g_cursor[N_NODES];
__device__ unsigned g_scan_state[SCAN_NB];    // decoupled-lookback state

// ---- per-block index dtype detection (int64 vs int32 edge buffers) ----
__device__ __forceinline__ int detect_is64_block(const unsigned int* buf) {
    __shared__ int s_is64;
    if (threadIdx.x < 32) {
        unsigned v = buf[2 * threadIdx.x + 1] | buf[2 * (threadIdx.x + 32) + 1];
#pragma unroll
        for (int o = 16; o; o >>= 1) v |= __shfl_xor_sync(0xFFFFFFFFu, v, o);
        if (threadIdx.x == 0) s_is64 = (v == 0) ? 1 : 0;
    }
    __syncthreads();
    return s_is64;
}

// ---- hist: zero lookback state + histogram destinations ----
__global__ void hist_kernel(const unsigned int* __restrict__ dstbuf,
                            int n, int* __restrict__ cnt) {
    int is64 = detect_is64_block(dstbuf);
    if (blockIdx.x == 0 && threadIdx.x < SCAN_NB) g_scan_state[threadIdx.x] = 0;
    int i = blockIdx.x * blockDim.x + threadIdx.x;
    if (i >= n) return;
    int d = (int)(is64 ? dstbuf[2 * i] : dstbuf[i]);
    atomicAdd(&cnt[d], 1);
}

// ---- single-pass exclusive scan, WARP-PARALLEL decoupled lookback ----
// flags: 0=invalid, 1=aggregate published, 2=inclusive prefix published
__global__ void scan_kernel(int* __restrict__ cnt, int n, int nE,
                            int* __restrict__ rowstart, int* __restrict__ cursor) {
    __shared__ int sh[256];
    __shared__ int s_exoff;
    const int t = threadIdx.x;
    const int b = blockIdx.x;
    const int i = b * 256 + t;

    int v = (i < n) ? cnt[i] : 0;
    if (i < n) cnt[i] = 0;            // reset for next call
    sh[t] = v;
    __syncthreads();
#pragma unroll
    for (int off = 1; off < 256; off <<= 1) {
        int x = (t >= off) ? sh[t - off] : 0;
        __syncthreads();
        sh[t] += x;
        __syncthreads();
    }
    int blocksum = sh[255];

    if (b == 0) {
        if (t == 0) {
            atomicExch(&g_scan_state[0], (2u << 30) | (unsigned)blocksum);
            s_exoff = 0;
        }
    } else {
        if (t == 0) atomicExch(&g_scan_state[b], (1u << 30) | (unsigned)blocksum);
        if (t < 32) {
            int sum = 0;
            int base = b;
            while (true) {
                int idx = base - 1 - t;
                unsigned s = (idx >= 0) ? atomicAdd(&g_scan_state[idx], 0u)
                                        : (2u << 30);
                unsigned flag = s >> 30;
                if (__any_sync(0xFFFFFFFFu, flag == 0u)) { __nanosleep(50); continue; }
                unsigned incmask = __ballot_sync(0xFFFFFFFFu, flag == 2u);
                int firstinc = __ffs(incmask) - 1;   // closest INC predecessor
                int contrib = (firstinc < 0 || t <= firstinc)
                                  ? (int)(s & 0x3FFFFFFFu) : 0;
#pragma unroll
                for (int o = 16; o; o >>= 1)
                    contrib += __shfl_xor_sync(0xFFFFFFFFu, contrib, o);
                sum += contrib;
                if (firstinc >= 0) break;
                base -= 32;
            }
            if (t == 0) {
                atomicExch(&g_scan_state[b], (2u << 30) | (unsigned)(sum + blocksum));
                s_exoff = sum;
            }
        }
    }
    __syncthreads();

    int ex = s_exoff + sh[t] - v;     // exclusive prefix
    if (i < n) { rowstart[i] = ex; cursor[i] = ex; }
    if (i == 0) rowstart[n] = nE;
}

// ---- fill CSR ----
__global__ void fill_kernel(const unsigned int* __restrict__ srcbuf,
                            const unsigned int* __restrict__ dstbuf,
                            int nE, int* __restrict__ cursor, int* __restrict__ csr) {
    int is64 = detect_is64_block(dstbuf);
    int e = blockIdx.x * blockDim.x + threadIdx.x;
    if (e >= nE) return;
    int s = (int)(is64 ? srcbuf[2 * e] : srcbuf[e]);
    int d = (int)(is64 ? dstbuf[2 * e] : dstbuf[e]);
    int pos = atomicAdd(&cursor[d], 1);
    csr[pos] = s;
}

// ---------------- tf32 helpers ----------------
__device__ __forceinline__ unsigned f2tf32(float f) {
    unsigned u;
    asm("cvt.rna.tf32.f32 %0, %1;" : "=r"(u) : "f"(f));
    return u;
}
__device__ __forceinline__ void cp_async16(void* sdst, const void* gsrc) {
    unsigned s = (unsigned)__cvta_generic_to_shared(sdst);
    asm volatile("cp.async.cg.shared.global [%0], [%1], 16;" :: "r"(s), "l"(gsrc));
}
__device__ __forceinline__ void mma_tf32(float* d, const unsigned* a, const unsigned* b) {
    asm volatile(
        "mma.sync.aligned.m16n8k8.row.col.f32.tf32.tf32.f32 "
        "{%0,%1,%2,%3}, {%4,%5,%6,%7}, {%8,%9}, {%0,%1,%2,%3};"
        : "+f"(d[0]), "+f"(d[1]), "+f"(d[2]), "+f"(d[3])
        : "r"(a[0]), "r"(a[1]), "r"(a[2]), "r"(a[3]), "r"(b[0]), "r"(b[1]));
}

// ---- W1 -> tf32, transposed [n][k'] with pair-interleave:
// k = ks*8 + t4 + 4h  ->  k' = ks*8 + t4*2 + h, so the (t4, t4+4) fragment
// pair becomes one contiguous float2 in smem.
__global__ void w1cvt_kernel(const float* __restrict__ W1, float* __restrict__ Wt) {
    int i = blockIdx.x * 256 + threadIdx.x;
    if (i >= IN_DIM * HID_DIM) return;
    int k = i >> 6;        // W1 is [512][64] row-major
    int n = i & 63;
    int kp = (k & ~7) | ((k & 3) << 1) | ((k >> 2) & 1);
    Wt[n * IN_DIM + kp] = __uint_as_float(f2tf32(W1[i]));
}

// ---------------- GEMM1 (tf32 tensor cores): H = X @ W1 ----------------
#define G1_BM 128
#define G1_BK 32
#define G1_ASTRIDE 36                 // conflict-free scalar a-frag loads
#define G1_BT_STRIDE 40               // conflict-free LDS.64 b-frag loads
#define G1_A_ELEMS (G1_BM * G1_ASTRIDE)
#define G1_B_ELEMS (64 * G1_BT_STRIDE)
#define G1_SMEM_BYTES ((2 * G1_A_ELEMS + 2 * G1_B_ELEMS) * 4)

__global__ __launch_bounds__(256) void gemm1_tf32_kernel(
    const float* __restrict__ X, const float* __restrict__ Wt,
    float* __restrict__ H, int M) {
    extern __shared__ float smem[];
    float* As = smem;
    float* Bs = smem + 2 * G1_A_ELEMS;

    const int tid = threadIdx.x;
    const int blockM = blockIdx.x * G1_BM;
    const int lane = tid & 31, warp = tid >> 5;
    const int g = lane >> 2, t4 = lane & 3;
    const int wm = warp & 3, wn = warp >> 2;

    auto load_chunk = [&](int st, int it) {
        const int k0 = it * G1_BK;
        float* as = As + st * G1_A_ELEMS;
        float* bs = Bs + st * G1_B_ELEMS;
#pragma unroll
        for (int j = 0; j < 4; j++) {
            int idx = tid + 256 * j;
            int r = idx >> 3, cv = idx & 7;
            int grow = blockM + r;
            if (grow > M - 1) grow = M - 1;
            cp_async16(as + r * G1_ASTRIDE + cv * 4,
                       X + (size_t)grow * IN_DIM + k0 + cv * 4);
        }
        // Wt is [64][512] (n-major, k'-interleaved); chunk = 32 consecutive k'
#pragma unroll
        for (int j = 0; j < 2; j++) {
            int idx = tid + 256 * j;
            int r = idx >> 3, cv = idx & 7;   // r = n row 0..63, cv = 0..7
            cp_async16(bs + r * G1_BT_STRIDE + cv * 4,
                       Wt + (size_t)r * IN_DIM + k0 + cv * 4);
        }
    };

    float acc[2][4][4];
#pragma unroll
    for (int mi = 0; mi < 2; mi++)
#pragma unroll
        for (int nj = 0; nj < 4; nj++)
#pragma unroll
            for (int q = 0; q < 4; q++) acc[mi][nj][q] = 0.f;

    const int NIT = IN_DIM / G1_BK;
    load_chunk(0, 0);
    asm volatile("cp.async.commit_group;");

    for (int it = 0; it < NIT; ++it) {
        if (it + 1 < NIT) {
            load_chunk((it + 1) & 1, it + 1);
            asm volatile("cp.async.commit_group;");
            asm volatile("cp.async.wait_group 1;");
        } else {
            asm volatile("cp.async.wait_group 0;");
        }
        __syncthreads();

        const float* as = As + (it & 1) * G1_A_ELEMS;
        const float* bs = Bs + (it & 1) * G1_B_ELEMS;
#pragma unroll
        for (int ks = 0; ks < 4; ks++) {
            const int kk = ks * 8;
            unsigned a[2][4];
#pragma unroll
            for (int mi = 0; mi < 2; mi++) {
                int rm = wm * 32 + mi * 16;
                a[mi][0] = f2tf32(as[(rm + g) * G1_ASTRIDE + kk + t4]);
                a[mi][1] = f2tf32(as[(rm + g + 8) * G1_ASTRIDE + kk + t4]);
                a[mi][2] = f2tf32(as[(rm + g) * G1_ASTRIDE + kk + t4 + 4]);
                a[mi][3] = f2tf32(as[(rm + g + 8) * G1_ASTRIDE + kk + t4 + 4]);
            }
            unsigned b[4][2];
#pragma unroll
            for (int nj = 0; nj < 4; nj++) {
                int nb = wn * 32 + nj * 8 + g;
                float2 bv = *(const float2*)(bs + nb * G1_BT_STRIDE + kk + t4 * 2);
                b[nj][0] = __float_as_uint(bv.x);
                b[nj][1] = __float_as_uint(bv.y);
            }
#pragma unroll
            for (int mi = 0; mi < 2; mi++)
#pragma unroll
                for (int nj = 0; nj < 4; nj++) mma_tf32(acc[mi][nj], a[mi], b[nj]);
        }
        __syncthreads();
    }

#pragma unroll
    for (int mi = 0; mi < 2; mi++) {
        int row0 = blockM + wm * 32 + mi * 16 + g;
        int row1 = row0 + 8;
#pragma unroll
        for (int nj = 0; nj < 4; nj++) {
            int col = wn * 32 + nj * 8 + t4 * 2;
            if (row0 < M)
                *(float2*)(H + (size_t)row0 * HID_DIM + col) =
                    make_float2(acc[mi][nj][0], acc[mi][nj][1]);
            if (row1 < M)
                *(float2*)(H + (size_t)row1 * HID_DIM + col) =
                    make_float2(acc[mi][nj][2], acc[mi][nj][3]);
        }
    }
}

// ---- fused: agg64 (gather, csr broadcast) + relu + GEMM2 -> h2 ----
#define F1_NODES 16
#define F1_AS_STRIDE 72
__global__ __launch_bounds__(256) void fused_agg64_gemm2_kernel(
    const float* __restrict__ h1, const int* __restrict__ rowstart,
    const int* __restrict__ csr, const float* __restrict__ W2,
    float* __restrict__ H2, int nNodes) {
    __shared__ float as[F1_NODES * F1_AS_STRIDE];
    __shared__ float ws[64 * 40];
    const int tid = threadIdx.x;
    const int nodeBase = blockIdx.x * F1_NODES;

    for (int i = tid; i < 64 * 40; i += 256) ws[i] = W2[i];

    {
        int nl = tid >> 4;               // node within block
        int c = tid & 15;                // float4 column / csr lane
        int node = nodeBase + nl;
        unsigned hmask = 0xFFFFu << (tid & 16);
        float4 acc = make_float4(0.f, 0.f, 0.f, 0.f);
        if (node < nNodes) {
            int j0 = rowstart[node];
            int end = rowstart[node + 1];
            for (int j = j0; j < end; j += 16) {
                int myi = j + c;
                int sv = (myi < end) ? csr[myi] : 0;
                int cnt = min(16, end - j);
                for (int q = 0; q < cnt; q++) {
                    int s = __shfl_sync(hmask, sv, q, 16);
                    float4 v = __ldg((const float4*)(h1 + (size_t)s * HID_DIM) + c);
                    acc.x += v.x; acc.y += v.y; acc.z += v.z; acc.w += v.w;
                }
            }
        }
        float* row = as + nl * F1_AS_STRIDE + c * 4;
        row[0] = fmaxf(acc.x, 0.f);
        row[1] = fmaxf(acc.y, 0.f);
        row[2] = fmaxf(acc.z, 0.f);
        row[3] = fmaxf(acc.w, 0.f);
    }
    __syncthreads();

    for (int o = tid; o < F1_NODES * 40; o += 256) {
        int r = o / 40, cc = o - r * 40;
        int node = nodeBase + r;
        if (node >= nNodes) break;
        const float* arow = as + r * F1_AS_STRIDE;
        float sum = 0.f;
#pragma unroll
        for (int k = 0; k < 64; k++) sum = fmaf(arow[k], ws[k * 40 + cc], sum);
        H2[(size_t)node * OUT_DIM + cc] = sum;
    }
}

// ---- fused: agg40 (gather, csr broadcast) + log_softmax -> out ----
#define F2_NODES 16
__global__ __launch_bounds__(256) void fused_agg40_lsm_kernel(
    const float* __restrict__ h2, const int* __restrict__ rowstart,
    const int* __restrict__ csr, float* __restrict__ out, int nNodes) {
    __shared__ float sh[F2_NODES][40];
    __shared__ float lval[F2_NODES];
    const int tid = threadIdx.x;
    const int nodeBase = blockIdx.x * F2_NODES;
    int nl = tid >> 4;
    int c = tid & 15;                    // lanes 0..9 carry float4 data
    int node = nodeBase + nl;
    unsigned hmask = 0xFFFFu << (tid & 16);
    bool active = (node < nNodes);

    if (active) {
        int j0 = rowstart[node];
        int end = rowstart[node + 1];
        float4 acc = make_float4(0.f, 0.f, 0.f, 0.f);
        for (int j = j0; j < end; j += 16) {
            int myi = j + c;
            int sv = (myi < end) ? csr[myi] : 0;
            int cnt = min(16, end - j);
            for (int q = 0; q < cnt; q++) {
                int s = __shfl_sync(hmask, sv, q, 16);
                if (c < 10) {
                    float4 v = __ldg((const float4*)(h2 + (size_t)s * OUT_DIM) + c);
                    acc.x += v.x; acc.y += v.y; acc.z += v.z; acc.w += v.w;
                }
            }
        }
        if (c < 10) {
            sh[nl][c * 4 + 0] = acc.x;
            sh[nl][c * 4 + 1] = acc.y;
            sh[nl][c * 4 + 2] = acc.z;
            sh[nl][c * 4 + 3] = acc.w;
        }
    }
    __syncthreads();

    if (active && c == 0) {
        float m = sh[nl][0];
#pragma unroll
        for (int k = 1; k < 40; k++) m = fmaxf(m, sh[nl][k]);
        float s = 0.f;
#pragma unroll
        for (int k = 0; k < 40; k++) s += __expf(sh[nl][k] - m);
        lval[nl] = m + __logf(s);
    }
    __syncthreads();

    if (active && c < 10) {
        float l = lval[nl];
        float4 v;
        v.x = sh[nl][c * 4 + 0] - l;
        v.y = sh[nl][c * 4 + 1] - l;
        v.z = sh[nl][c * 4 + 2] - l;
        v.w = sh[nl][c * 4 + 3] - l;
        *((float4*)(out + (size_t)node * OUT_DIM) + c) = v;
    }
}

// ---------------- launch ----------------
extern "C" void kernel_launch(void* const* d_in, const int* in_sizes, int n_in,
                              void* d_out, int out_size) {
    const float* x  = (const float*)d_in[0];
    const unsigned int* srcbuf = (const unsigned int*)d_in[1];
    const unsigned int* dstbuf = (const unsigned int*)d_in[2];
    const float* W1 = (const float*)d_in[3];
    const float* W2 = (const float*)d_in[4];
    float* out = (float*)d_out;

    const int M = in_sizes[0] / IN_DIM;      // 50000
    const int nE = in_sizes[1];              // 800000

    float* h1   = nullptr; cudaGetSymbolAddress((void**)&h1,   g_h1);
    float* h2   = nullptr; cudaGetSymbolAddress((void**)&h2,   g_h2);
    float* w1t  = nullptr; cudaGetSymbolAddress((void**)&w1t,  g_w1t);
    int* csr    = nullptr; cudaGetSymbolAddress((void**)&csr,  g_csr);
    int* cnt    = nullptr; cudaGetSymbolAddress((void**)&cnt,  g_cnt);
    int* rows   = nullptr; cudaGetSymbolAddress((void**)&rows, g_rowstart);
    int* cur    = nullptr; cudaGetSymbolAddress((void**)&cur,  g_cursor);

    cudaFuncSetAttribute(gemm1_tf32_kernel,
                         cudaFuncAttributeMaxDynamicSharedMemorySize, G1_SMEM_BYTES);

    // fork a side stream for GEMM1 (independent of CSR build)
    cudaStream_t s2;
    cudaStreamCreateWithFlags(&s2, cudaStreamNonBlocking);
    cudaEvent_t evFork, evJoin;
    cudaEventCreateWithFlags(&evFork, cudaEventDisableTiming);
    cudaEventCreateWithFlags(&evJoin, cudaEventDisableTiming);

    cudaEventRecord(evFork, 0);
    cudaStreamWaitEvent(s2, evFork, 0);

    // ---- branch B (s2): W1 tf32 transpose/interleave + GEMM1 ----
    w1cvt_kernel<<<(IN_DIM * HID_DIM + 255) / 256, 256, 0, s2>>>(W1, w1t);
    gemm1_tf32_kernel<<<(M + G1_BM - 1) / G1_BM, 256, G1_SMEM_BYTES, s2>>>(
        x, w1t, h1, M);
    cudaEventRecord(evJoin, s2);

    // ---- branch A (stream 0): CSR build ----
    hist_kernel<<<(nE + 255) / 256, 256>>>(dstbuf, nE, cnt);
    scan_kernel<<<SCAN_NB, 256>>>(cnt, M, nE, rows, cur);
    fill_kernel<<<(nE + 255) / 256, 256>>>(srcbuf, dstbuf, nE, cur, csr);

    // ---- join ----
    cudaStreamWaitEvent(0, evJoin, 0);

    // ---- fused layer-1 aggregation + relu + GEMM2 ----
    fused_agg64_gemm2_kernel<<<(M + F1_NODES - 1) / F1_NODES, 256>>>(
        h1, rows, csr, W2, h2, M);

    // ---- fused layer-2 aggregation + log_softmax ----
    fused_agg40_lsm_kernel<<<(M + F2_NODES - 1) / F2_NODES, 256>>>(
        h2, rows, csr, out, M);

    // NOTE: s2/evFork/evJoin intentionally not destroyed — destroying stream
    // or events referenced by an in-progress capture invalidates the graph.
    // Host-side objects only (no device memory); created twice per test run.
}

// round 16
// speedup vs baseline: 1.1309x; 1.1309x over previous
#include <cuda_runtime.h>
#include <cuda_bf16.h>
#include <math.h>

#define N_NODES 50000
#define N_EDGES 800000
#define IN_DIM 512
#define HID_DIM 64
#define OUT_DIM 40
#define SCAN_NB ((N_NODES + 255) / 256)   // 196

// ---------------- scratch (no allocations allowed) ----------------
__device__ float g_h1[N_NODES * HID_DIM];     // x @ W1
__device__ float g_h2[N_NODES * OUT_DIM];     // relu(agg1) @ W2
__device__ float g_w1tf[IN_DIM * HID_DIM];    // W1 rounded to tf32
__device__ int   g_csr[N_EDGES];              // src ids grouped by dst
__device__ int   g_cnt[N_NODES];              // per-dst degree (zeroed inside scan)
__device__ int   g_rowstart[N_NODES + 1];
__device__ int   g_cursor[N_NODES];
__device__ unsigned g_scan_state[SCAN_NB];    // decoupled-lookback state

// ---- per-block index dtype detection (int64 vs int32 edge buffers) ----
__device__ __forceinline__ int detect_is64_block(const unsigned int* buf) {
    __shared__ int s_is64;
    if (threadIdx.x < 32) {
        unsigned v = buf[2 * threadIdx.x + 1] | buf[2 * (threadIdx.x + 32) + 1];
#pragma unroll
        for (int o = 16; o; o >>= 1) v |= __shfl_xor_sync(0xFFFFFFFFu, v, o);
        if (threadIdx.x == 0) s_is64 = (v == 0) ? 1 : 0;
    }
    __syncthreads();
    return s_is64;
}

// ---- hist: zero lookback state + histogram destinations ----
__global__ void hist_kernel(const unsigned int* __restrict__ dstbuf,
                            int n, int* __restrict__ cnt) {
    int is64 = detect_is64_block(dstbuf);
    if (blockIdx.x == 0 && threadIdx.x < SCAN_NB) g_scan_state[threadIdx.x] = 0;
    int i = blockIdx.x * blockDim.x + threadIdx.x;
    if (i >= n) return;
    int d = (int)(is64 ? dstbuf[2 * i] : dstbuf[i]);
    atomicAdd(&cnt[d], 1);
}

// ---- single-pass exclusive scan, WARP-PARALLEL decoupled lookback ----
// flags: 0=invalid, 1=aggregate published, 2=inclusive prefix published
__global__ void scan_kernel(int* __restrict__ cnt, int n, int nE,
                            int* __restrict__ rowstart, int* __restrict__ cursor) {
    __shared__ int sh[256];
    __shared__ int s_exoff;
    const int t = threadIdx.x;
    const int b = blockIdx.x;
    const int i = b * 256 + t;

    int v = (i < n) ? cnt[i] : 0;
    if (i < n) cnt[i] = 0;            // reset for next call
    sh[t] = v;
    __syncthreads();
#pragma unroll
    for (int off = 1; off < 256; off <<= 1) {
        int x = (t >= off) ? sh[t - off] : 0;
        __syncthreads();
        sh[t] += x;
        __syncthreads();
    }
    int blocksum = sh[255];

    if (b == 0) {
        if (t == 0) {
            atomicExch(&g_scan_state[0], (2u << 30) | (unsigned)blocksum);
            s_exoff = 0;
        }
    } else {
        if (t == 0) atomicExch(&g_scan_state[b], (1u << 30) | (unsigned)blocksum);
        if (t < 32) {
            int sum = 0;
            int base = b;
            while (true) {
                int idx = base - 1 - t;
                unsigned s = (idx >= 0) ? atomicAdd(&g_scan_state[idx], 0u)
                                        : (2u << 30);
                unsigned flag = s >> 30;
                if (__any_sync(0xFFFFFFFFu, flag == 0u)) { __nanosleep(50); continue; }
                unsigned incmask = __ballot_sync(0xFFFFFFFFu, flag == 2u);
                int firstinc = __ffs(incmask) - 1;   // closest INC predecessor
                int contrib = (firstinc < 0 || t <= firstinc)
                                  ? (int)(s & 0x3FFFFFFFu) : 0;
#pragma unroll
                for (int o = 16; o; o >>= 1)
                    contrib += __shfl_xor_sync(0xFFFFFFFFu, contrib, o);
                sum += contrib;
                if (firstinc >= 0) break;
                base -= 32;
            }
            if (t == 0) {
                atomicExch(&g_scan_state[b], (2u << 30) | (unsigned)(sum + blocksum));
                s_exoff = sum;
            }
        }
    }
    __syncthreads();

    int ex = s_exoff + sh[t] - v;     // exclusive prefix
    if (i < n) { rowstart[i] = ex; cursor[i] = ex; }
    if (i == 0) rowstart[n] = nE;
}

// ---- fill CSR ----
__global__ void fill_kernel(const unsigned int* __restrict__ srcbuf,
                            const unsigned int* __restrict__ dstbuf,
                            int nE, int* __restrict__ cursor, int* __restrict__ csr) {
    int is64 = detect_is64_block(dstbuf);
    int e = blockIdx.x * blockDim.x + threadIdx.x;
    if (e >= nE) return;
    int s = (int)(is64 ? srcbuf[2 * e] : srcbuf[e]);
    int d = (int)(is64 ? dstbuf[2 * e] : dstbuf[e]);
    int pos = atomicAdd(&cursor[d], 1);
    csr[pos] = s;
}

// ---------------- tf32 helpers ----------------
__device__ __forceinline__ unsigned f2tf32(float f) {
    unsigned u;
    asm("cvt.rna.tf32.f32 %0, %1;" : "=r"(u) : "f"(f));
    return u;
}
__device__ __forceinline__ void cp_async16(void* sdst, const void* gsrc) {
    unsigned s = (unsigned)__cvta_generic_to_shared(sdst);
    asm volatile("cp.async.cg.shared.global [%0], [%1], 16;" :: "r"(s), "l"(gsrc));
}
__device__ __forceinline__ void mma_tf32(float* d, const unsigned* a, const unsigned* b) {
    asm volatile(
        "mma.sync.aligned.m16n8k8.row.col.f32.tf32.tf32.f32 "
        "{%0,%1,%2,%3}, {%4,%5,%6,%7}, {%8,%9}, {%0,%1,%2,%3};"
        : "+f"(d[0]), "+f"(d[1]), "+f"(d[2]), "+f"(d[3])
        : "r"(a[0]), "r"(a[1]), "r"(a[2]), "r"(a[3]), "r"(b[0]), "r"(b[1]));
}

// ---- pre-round W1 to tf32 (removes b-fragment cvts from gemm1 hot loop) ----
__global__ void w1cvt_kernel(const float* __restrict__ W1, float* __restrict__ Wtf) {
    int i = blockIdx.x * 256 + threadIdx.x;
    if (i < IN_DIM * HID_DIM) Wtf[i] = __uint_as_float(f2tf32(W1[i]));
}

// ---------------- GEMM1 (tf32 tensor cores): H = X @ W1 ----------------
#define G1_BM 128
#define G1_BK 32
#define G1_ASTRIDE 36
#define G1_BSTRIDE 72
#define G1_A_ELEMS (G1_BM * G1_ASTRIDE)
#define G1_B_ELEMS (G1_BK * G1_BSTRIDE)
#define G1_SMEM_BYTES ((2 * G1_A_ELEMS + 2 * G1_B_ELEMS) * 4)

__global__ __launch_bounds__(256) void gemm1_tf32_kernel(
    const float* __restrict__ X, const float* __restrict__ Wtf,
    float* __restrict__ H, int M) {
    extern __shared__ float smem[];
    float* As = smem;
    float* Bs = smem + 2 * G1_A_ELEMS;

    const int tid = threadIdx.x;
    const int blockM = blockIdx.x * G1_BM;
    const int lane = tid & 31, warp = tid >> 5;
    const int g = lane >> 2, t4 = lane & 3;
    const int wm = warp & 3, wn = warp >> 2;

    auto load_chunk = [&](int st, int it) {
        const int k0 = it * G1_BK;
        float* as = As + st * G1_A_ELEMS;
        float* bs = Bs + st * G1_B_ELEMS;
#pragma unroll
        for (int j = 0; j < 4; j++) {
            int idx = tid + 256 * j;
            int r = idx >> 3, cv = idx & 7;
            int grow = blockM + r;
            if (grow > M - 1) grow = M - 1;
            cp_async16(as + r * G1_ASTRIDE + cv * 4,
                       X + (size_t)grow * IN_DIM + k0 + cv * 4);
        }
#pragma unroll
        for (int j = 0; j < 2; j++) {
            int idx = tid + 256 * j;
            int r = idx >> 4, cv = idx & 15;
            cp_async16(bs + r * G1_BSTRIDE + cv * 4,
                       Wtf + (size_t)(k0 + r) * HID_DIM + cv * 4);
        }
    };

    float acc[2][4][4];
#pragma unroll
    for (int mi = 0; mi < 2; mi++)
#pragma unroll
        for (int nj = 0; nj < 4; nj++)
#pragma unroll
            for (int q = 0; q < 4; q++) acc[mi][nj][q] = 0.f;

    const int NIT = IN_DIM / G1_BK;
    load_chunk(0, 0);
    asm volatile("cp.async.commit_group;");

    for (int it = 0; it < NIT; ++it) {
        if (it + 1 < NIT) {
            load_chunk((it + 1) & 1, it + 1);
            asm volatile("cp.async.commit_group;");
            asm volatile("cp.async.wait_group 1;");
        } else {
            asm volatile("cp.async.wait_group 0;");
        }
        __syncthreads();

        const float* as = As + (it & 1) * G1_A_ELEMS;
        const float* bs = Bs + (it & 1) * G1_B_ELEMS;
#pragma unroll
        for (int ks = 0; ks < 4; ks++) {
            const int kk = ks * 8;
            unsigned a[2][4];
#pragma unroll
            for (int mi = 0; mi < 2; mi++) {
                int rm = wm * 32 + mi * 16;
                a[mi][0] = f2tf32(as[(rm + g) * G1_ASTRIDE + kk + t4]);
                a[mi][1] = f2tf32(as[(rm + g + 8) * G1_ASTRIDE + kk + t4]);
                a[mi][2] = f2tf32(as[(rm + g) * G1_ASTRIDE + kk + t4 + 4]);
                a[mi][3] = f2tf32(as[(rm + g + 8) * G1_ASTRIDE + kk + t4 + 4]);
            }
            unsigned b[4][2];
#pragma unroll
            for (int nj = 0; nj < 4; nj++) {
                int nb = wn * 32 + nj * 8 + g;
                b[nj][0] = __float_as_uint(bs[(kk + t4) * G1_BSTRIDE + nb]);
                b[nj][1] = __float_as_uint(bs[(kk + t4 + 4) * G1_BSTRIDE + nb]);
            }
#pragma unroll
            for (int mi = 0; mi < 2; mi++)
#pragma unroll
                for (int nj = 0; nj < 4; nj++) mma_tf32(acc[mi][nj], a[mi], b[nj]);
        }
        __syncthreads();
    }

#pragma unroll
    for (int mi = 0; mi < 2; mi++) {
        int row0 = blockM + wm * 32 + mi * 16 + g;
        int row1 = row0 + 8;
#pragma unroll
        for (int nj = 0; nj < 4; nj++) {
            int col = wn * 32 + nj * 8 + t4 * 2;
            if (row0 < M)
                *(float2*)(H + (size_t)row0 * HID_DIM + col) =
                    make_float2(acc[mi][nj][0], acc[mi][nj][1]);
            if (row1 < M)
                *(float2*)(H + (size_t)row1 * HID_DIM + col) =
                    make_float2(acc[mi][nj][2], acc[mi][nj][3]);
        }
    }
}

// ---- fused: agg64 (gather) + relu + GEMM2 -> h2, 16 nodes/block ----
#define F1_NODES 16
#define F1_AS_STRIDE 72
__global__ __launch_bounds__(256) void fused_agg64_gemm2_kernel(
    const float* __restrict__ h1, const int* __restrict__ rowstart,
    const int* __restrict__ csr, const float* __restrict__ W2,
    float* __restrict__ H2, int nNodes) {
    __shared__ float as[F1_NODES * F1_AS_STRIDE];
    __shared__ float ws[64 * 40];
    const int tid = threadIdx.x;
    const int nodeBase = blockIdx.x * F1_NODES;

    for (int i = tid; i < 64 * 40; i += 256) ws[i] = W2[i];

    {
        int nl = tid >> 4;
        int c = tid & 15;
        int node = nodeBase + nl;
        float4 acc = make_float4(0.f, 0.f, 0.f, 0.f);
        if (node < nNodes) {
            int j = rowstart[node];
            int end = rowstart[node + 1];
            for (; j + 1 < end; j += 2) {
                int s0 = csr[j], s1 = csr[j + 1];
                float4 v0 = __ldg((const float4*)(h1 + (size_t)s0 * HID_DIM) + c);
                float4 v1 = __ldg((const float4*)(h1 + (size_t)s1 * HID_DIM) + c);
                acc.x += v0.x + v1.x; acc.y += v0.y + v1.y;
                acc.z += v0.z + v1.z; acc.w += v0.w + v1.w;
            }
            if (j < end) {
                int s0 = csr[j];
                float4 v0 = __ldg((const float4*)(h1 + (size_t)s0 * HID_DIM) + c);
                acc.x += v0.x; acc.y += v0.y; acc.z += v0.z; acc.w += v0.w;
            }
        }
        float* row = as + nl * F1_AS_STRIDE + c * 4;
        row[0] = fmaxf(acc.x, 0.f);
        row[1] = fmaxf(acc.y, 0.f);
        row[2] = fmaxf(acc.z, 0.f);
        row[3] = fmaxf(acc.w, 0.f);
    }
    __syncthreads();

    for (int o = tid; o < F1_NODES * 40; o += 256) {
        int r = o / 40, cc = o - r * 40;
        int node = nodeBase + r;
        if (node >= nNodes) break;
        const float* arow = as + r * F1_AS_STRIDE;
        float sum = 0.f;
#pragma unroll
        for (int k = 0; k < 64; k++) sum = fmaf(arow[k], ws[k * 40 + cc], sum);
        H2[(size_t)node * OUT_DIM + cc] = sum;
    }
}

// ---- fused: agg40 (gather) + log_softmax -> out, 25 nodes/block ----
#define F2_NODES 25
__global__ __launch_bounds__(256) void fused_agg40_lsm_kernel(
    const float* __restrict__ h2, const int* __restrict__ rowstart,
    const int* __restrict__ csr, float* __restrict__ out, int nNodes) {
    __shared__ float sh[F2_NODES][40];
    __shared__ float lval[F2_NODES];
    const int tid = threadIdx.x;
    const int nodeBase = blockIdx.x * F2_NODES;
    int nl = tid / 10;
    int c = tid - nl * 10;
    int node = nodeBase + nl;
    bool active = (nl < F2_NODES) && (node < nNodes);

    if (active) {
        int j = rowstart[node];
        int end = rowstart[node + 1];
        float4 acc = make_float4(0.f, 0.f, 0.f, 0.f);
        for (; j + 1 < end; j += 2) {
            int s0 = csr[j], s1 = csr[j + 1];
            float4 v0 = __ldg((const float4*)(h2 + (size_t)s0 * OUT_DIM) + c);
            float4 v1 = __ldg((const float4*)(h2 + (size_t)s1 * OUT_DIM) + c);
            acc.x += v0.x + v1.x; acc.y += v0.y + v1.y;
            acc.z += v0.z + v1.z; acc.w += v0.w + v1.w;
        }
        if (j < end) {
            int s0 = csr[j];
            float4 v0 = __ldg((const float4*)(h2 + (size_t)s0 * OUT_DIM) + c);
            acc.x += v0.x; acc.y += v0.y; acc.z += v0.z; acc.w += v0.w;
        }
        sh[nl][c * 4 + 0] = acc.x;
        sh[nl][c * 4 + 1] = acc.y;
        sh[nl][c * 4 + 2] = acc.z;
        sh[nl][c * 4 + 3] = acc.w;
    }
    __syncthreads();

    if (active && c == 0) {
        float m = sh[nl][0];
#pragma unroll
        for (int k = 1; k < 40; k++) m = fmaxf(m, sh[nl][k]);
        float s = 0.f;
#pragma unroll
        for (int k = 0; k < 40; k++) s += __expf(sh[nl][k] - m);
        lval[nl] = m + __logf(s);
    }
    __syncthreads();

    if (active) {
        float l = lval[nl];
        float4 v;
        v.x = sh[nl][c * 4 + 0] - l;
        v.y = sh[nl][c * 4 + 1] - l;
        v.z = sh[nl][c * 4 + 2] - l;
        v.w = sh[nl][c * 4 + 3] - l;
        *((float4*)(out + (size_t)node * OUT_DIM) + c) = v;
    }
}

// ---------------- launch ----------------
extern "C" void kernel_launch(void* const* d_in, const int* in_sizes, int n_in,
                              void* d_out, int out_size) {
    const float* x  = (const float*)d_in[0];
    const unsigned int* srcbuf = (const unsigned int*)d_in[1];
    const unsigned int* dstbuf = (const unsigned int*)d_in[2];
    const float* W1 = (const float*)d_in[3];
    const float* W2 = (const float*)d_in[4];
    float* out = (float*)d_out;

    const int M = in_sizes[0] / IN_DIM;      // 50000
    const int nE = in_sizes[1];              // 800000

    float* h1   = nullptr; cudaGetSymbolAddress((void**)&h1,   g_h1);
    float* h2   = nullptr; cudaGetSymbolAddress((void**)&h2,   g_h2);
    float* w1tf = nullptr; cudaGetSymbolAddress((void**)&w1tf, g_w1tf);
    int* csr    = nullptr; cudaGetSymbolAddress((void**)&csr,  g_csr);
    int* cnt    = nullptr; cudaGetSymbolAddress((void**)&cnt,  g_cnt);
    int* rows   = nullptr; cudaGetSymbolAddress((void**)&rows, g_rowstart);
    int* cur    = nullptr; cudaGetSymbolAddress((void**)&cur,  g_cursor);

    cudaFuncSetAttribute(gemm1_tf32_kernel,
                         cudaFuncAttributeMaxDynamicSharedMemorySize, G1_SMEM_BYTES);

    // fork a side stream for GEMM1 (independent of CSR build)
    cudaStream_t s2;
    cudaStreamCreateWithFlags(&s2, cudaStreamNonBlocking);
    cudaEvent_t evFork, evJoin;
    cudaEventCreateWithFlags(&evFork, cudaEventDisableTiming);
    cudaEventCreateWithFlags(&evJoin, cudaEventDisableTiming);

    cudaEventRecord(evFork, 0);
    cudaStreamWaitEvent(s2, evFork, 0);

    // ---- branch B (s2): W1 tf32 conversion + GEMM1 ----
    w1cvt_kernel<<<(IN_DIM * HID_DIM + 255) / 256, 256, 0, s2>>>(W1, w1tf);
    gemm1_tf32_kernel<<<(M + G1_BM - 1) / G1_BM, 256, G1_SMEM_BYTES, s2>>>(
        x, w1tf, h1, M);
    cudaEventRecord(evJoin, s2);

    // ---- branch A (stream 0): CSR build ----
    hist_kernel<<<(nE + 255) / 256, 256>>>(dstbuf, nE, cnt);
    scan_kernel<<<SCAN_NB, 256>>>(cnt, M, nE, rows, cur);
    fill_kernel<<<(nE + 255) / 256, 256>>>(srcbuf, dstbuf, nE, cur, csr);

    // ---- join ----
    cudaStreamWaitEvent(0, evJoin, 0);

    // ---- fused layer-1 aggregation + relu + GEMM2 ----
    fused_agg64_gemm2_kernel<<<(M + F1_NODES - 1) / F1_NODES, 256>>>(
        h1, rows, csr, W2, h2, M);

    // ---- fused layer-2 aggregation + log_softmax ----
    fused_agg40_lsm_kernel<<<(M + F2_NODES - 1) / F2_NODES, 256>>>(
        h2, rows, csr, out, M);

    // NOTE: s2/evFork/evJoin intentionally not destroyed — destroying stream
    // or events referenced by an in-progress capture invalidates the graph.
    // Host-side objects only (no device memory); created twice per test run.
}